// round 9
// baseline (speedup 1.0000x reference)
#include <cuda_runtime.h>
#include <cstdint>

#define BATCH 4
#define SEQ   2048
#define NH    16
#define DH    64
#define DM    1024
#define MROWS (BATCH*SEQ)

__device__ float g_q[(size_t)BATCH*NH*SEQ*DH];
__device__ float g_k[(size_t)BATCH*NH*SEQ*DH];
__device__ float g_v[(size_t)BATCH*NH*SEQ*DH];
__device__ float g_o[(size_t)MROWS*DM];
__device__ float g_wt[(size_t)3*DM*DM];   // [wz][h*64+d][m]  (transposed weights)
__device__ float g_owt[(size_t)DM*DM];    // [n][k]

__device__ __forceinline__ uint32_t f2tf(float x) {
    uint32_t u;
    asm("cvt.rna.tf32.f32 %0, %1;" : "=r"(u) : "f"(x));
    return u;
}
__device__ __forceinline__ float f2tff(float x) { return __uint_as_float(f2tf(x)); }

__device__ __forceinline__ void mma_tf32(float* c,
    uint32_t a0, uint32_t a1, uint32_t a2, uint32_t a3,
    uint32_t b0, uint32_t b1)
{
    asm volatile(
        "mma.sync.aligned.m16n8k8.row.col.f32.tf32.tf32.f32 "
        "{%0,%1,%2,%3}, {%4,%5,%6,%7}, {%8,%9}, {%0,%1,%2,%3};"
        : "+f"(c[0]), "+f"(c[1]), "+f"(c[2]), "+f"(c[3])
        : "r"(a0), "r"(a1), "r"(a2), "r"(a3), "r"(b0), "r"(b1));
}

// ---------------- weight transpose prep ----------------
__global__ __launch_bounds__(256) void prep_kernel(
    const float* __restrict__ Qw, const float* __restrict__ Kw,
    const float* __restrict__ Vw, const float* __restrict__ Ow)
{
    __shared__ float t[32][33];
    const int z = blockIdx.z;
    const float* src; float* dst; int sC, dC;
    int r0 = blockIdx.x * 32, c0 = blockIdx.y * 32;
    if (z < 48) {
        if (blockIdx.y >= 2) return;
        int wz = z >> 4, h = z & 15;
        src = (wz == 0 ? Qw : wz == 1 ? Kw : Vw) + (size_t)h * DM * DH;
        dst = g_wt + (size_t)wz * DM * DM + (size_t)h * DH * DM;
        sC = DH; dC = DM;
    } else {
        src = Ow; dst = g_owt; sC = DM; dC = DM;
    }
    const int tx = threadIdx.x & 31, ty0 = threadIdx.x >> 5;
#pragma unroll
    for (int i = 0; i < 4; i++)
        t[ty0 + i * 8][tx] = src[(size_t)(r0 + ty0 + i * 8) * sC + c0 + tx];
    __syncthreads();
#pragma unroll
    for (int i = 0; i < 4; i++)
        dst[(size_t)(c0 + ty0 + i * 8) * dC + r0 + tx] = t[tx][ty0 + i * 8];
}

// ---------------- GEMM with k-pair interleaved smem ----------------
// Layout: row-major tiles [128 rows][32 k], k stored interleaved:
// position of k within 8-group = (k&3)*2 + (k>>2). Stride 40 floats.
#define SP 40
#define TILE_FLOATS (128 * SP)          // 5120
#define STAGE_FLOATS (2 * TILE_FLOATS)  // A then B
#define GEMM_SMEM (2 * STAGE_FLOATS * 4)  // 81920 B

__device__ __forceinline__ void sts_group(float* dst, float4 p, float4 q) {
    // p = k 0..3, q = k 4..7 -> interleaved {k0,k4,k1,k5},{k2,k6,k3,k7}
    float4 u = make_float4(f2tff(p.x), f2tff(q.x), f2tff(p.y), f2tff(q.y));
    float4 v = make_float4(f2tff(p.z), f2tff(q.z), f2tff(p.w), f2tff(q.w));
    *(float4*)dst = u;
    *(float4*)(dst + 4) = v;
}

// A: [m0..m0+127][k] stride DM.  Bt: [n0..n0+127][k] stride DM.
__device__ __forceinline__ void gemm128(
    float* sm, const float* __restrict__ A, const float* __restrict__ Bt,
    float c[2][8][4])
{
    const int tid  = threadIdx.x;
    const int lane = tid & 31;
    const int w    = tid >> 5;
    const int wm   = w >> 1;
    const int wn   = w & 1;
    const int g    = lane >> 2;
    const int t    = lane & 3;

    const int lrow = tid >> 2;        // 0..63, +64 for second half
    const int lkg  = tid & 3;         // 8k-group within 32

    // frag word offsets
    const int a_off = (wm * 32 + g) * SP + 2 * t;
    const int b_off = (wn * 64 + g) * SP + 2 * t;

    float4 av[2][2], bv[2][2];
#pragma unroll
    for (int i = 0; i < 2; i++) {
        const float* pa = A + (size_t)(lrow + i * 64) * DM + lkg * 8;
        av[i][0] = *(const float4*)pa;  av[i][1] = *(const float4*)(pa + 4);
        const float* pb = Bt + (size_t)(lrow + i * 64) * DM + lkg * 8;
        bv[i][0] = *(const float4*)pb;  bv[i][1] = *(const float4*)(pb + 4);
    }
    // stage 0
#pragma unroll
    for (int i = 0; i < 2; i++) {
        sts_group(sm + (lrow + i * 64) * SP + lkg * 8, av[i][0], av[i][1]);
        sts_group(sm + TILE_FLOATS + (lrow + i * 64) * SP + lkg * 8, bv[i][0], bv[i][1]);
    }

    for (int it = 0; it < 32; it++) {
        __syncthreads();
        const bool more = (it + 1 < 32);
        if (more) {
            const int kn = (it + 1) * 32;
#pragma unroll
            for (int i = 0; i < 2; i++) {
                const float* pa = A + (size_t)(lrow + i * 64) * DM + kn + lkg * 8;
                av[i][0] = *(const float4*)pa;  av[i][1] = *(const float4*)(pa + 4);
                const float* pb = Bt + (size_t)(lrow + i * 64) * DM + kn + lkg * 8;
                bv[i][0] = *(const float4*)pb;  bv[i][1] = *(const float4*)(pb + 4);
            }
        }

        const float* As = sm + (it & 1) * STAGE_FLOATS;
        const float* Bs = As + TILE_FLOATS;
#pragma unroll
        for (int ks = 0; ks < 4; ks++) {
            uint32_t a[2][4];
#pragma unroll
            for (int mt = 0; mt < 2; mt++) {
                float2 r0 = *(const float2*)(As + a_off + mt * (16 * SP) + ks * 8);
                float2 r1 = *(const float2*)(As + a_off + mt * (16 * SP) + 8 * SP + ks * 8);
                a[mt][0] = __float_as_uint(r0.x);
                a[mt][1] = __float_as_uint(r1.x);
                a[mt][2] = __float_as_uint(r0.y);
                a[mt][3] = __float_as_uint(r1.y);
            }
#pragma unroll
            for (int nt = 0; nt < 8; nt++) {
                float2 bp = *(const float2*)(Bs + b_off + nt * (8 * SP) + ks * 8);
                uint32_t b0 = __float_as_uint(bp.x);
                uint32_t b1 = __float_as_uint(bp.y);
#pragma unroll
                for (int mt = 0; mt < 2; mt++)
                    mma_tf32(c[mt][nt], a[mt][0], a[mt][1], a[mt][2], a[mt][3], b0, b1);
            }
        }

        if (more) {
            float* st = sm + ((it + 1) & 1) * STAGE_FLOATS;
#pragma unroll
            for (int i = 0; i < 2; i++) {
                sts_group(st + (lrow + i * 64) * SP + lkg * 8, av[i][0], av[i][1]);
                sts_group(st + TILE_FLOATS + (lrow + i * 64) * SP + lkg * 8, bv[i][0], bv[i][1]);
            }
        }
    }
}

// ---------------------------------------------------------------------------
// QKV projection: 128x128 tile (2 heads)
// ---------------------------------------------------------------------------
__global__ __launch_bounds__(256) void qkv_kernel(
    const float* __restrict__ X,
    const float* __restrict__ Qb, const float* __restrict__ Kb,
    const float* __restrict__ Vb)
{
    extern __shared__ float sm[];
    const int m0    = blockIdx.x * 128;
    const int hp    = blockIdx.y;
    const int which = blockIdx.z;

    const float* bias = (which == 0 ? Qb : which == 1 ? Kb : Vb);
    float* Out        = (which == 0 ? g_q : which == 1 ? g_k : g_v);
    const float* Bt   = g_wt + (size_t)which * DM * DM + (size_t)hp * 128 * DM;

    float c[2][8][4];
#pragma unroll
    for (int mt = 0; mt < 2; mt++)
#pragma unroll
        for (int nt = 0; nt < 8; nt++)
#pragma unroll
            for (int i = 0; i < 4; i++) c[mt][nt][i] = 0.f;

    gemm128(sm, X + (size_t)m0 * DM, Bt, c);

    const int tid  = threadIdx.x;
    const int lane = tid & 31;
    const int w    = tid >> 5;
    const int wm   = w >> 1, wn = w & 1;
    const int g    = lane >> 2, t = lane & 3;

    const int h = 2 * hp + wn;
    const float* bi = bias + h * DH;
#pragma unroll
    for (int mt = 0; mt < 2; mt++) {
        int m = m0 + wm * 32 + mt * 16 + g;
        int b_ = m >> 11, p = m & 2047;
        float* dst = Out + (((size_t)(b_ * NH + h)) * SEQ + p) * DH;
#pragma unroll
        for (int nt = 0; nt < 8; nt++) {
            int d = nt * 8 + 2 * t;
            float bx = bi[d], by = bi[d + 1];
            float2 v0 = { c[mt][nt][0] + bx, c[mt][nt][1] + by };
            float2 v1 = { c[mt][nt][2] + bx, c[mt][nt][3] + by };
            *(float2*)&dst[d]          = v0;
            *(float2*)&dst[8 * DH + d] = v1;
        }
    }
}

// ---------------------------------------------------------------------------
// Output projection: 128x128 tile
// ---------------------------------------------------------------------------
__global__ __launch_bounds__(256) void oproj_kernel(
    const float* __restrict__ Ob, float* __restrict__ out)
{
    extern __shared__ float sm[];
    const int m0 = blockIdx.x * 128;
    const int n0 = blockIdx.y * 128;

    float c[2][8][4];
#pragma unroll
    for (int mt = 0; mt < 2; mt++)
#pragma unroll
        for (int nt = 0; nt < 8; nt++)
#pragma unroll
            for (int i = 0; i < 4; i++) c[mt][nt][i] = 0.f;

    gemm128(sm, g_o + (size_t)m0 * DM, g_owt + (size_t)n0 * DM, c);

    const int tid  = threadIdx.x;
    const int lane = tid & 31;
    const int w    = tid >> 5;
    const int wm   = w >> 1, wn = w & 1;
    const int g    = lane >> 2, t = lane & 3;

#pragma unroll
    for (int mt = 0; mt < 2; mt++) {
        int m = m0 + wm * 32 + mt * 16 + g;
        float* dst = out + (size_t)m * DM + n0 + wn * 64;
        const float* bi = Ob + n0 + wn * 64;
#pragma unroll
        for (int nt = 0; nt < 8; nt++) {
            int d = nt * 8 + 2 * t;
            float bx = bi[d], by = bi[d + 1];
            float2 v0 = { c[mt][nt][0] + bx, c[mt][nt][1] + by };
            float2 v1 = { c[mt][nt][2] + bx, c[mt][nt][3] + by };
            *(float2*)&dst[d]          = v0;
            *(float2*)&dst[8 * DM + d] = v1;
        }
    }
}

// ---------------------------------------------------------------------------
// Causal flash attention (unchanged from R8)
// ---------------------------------------------------------------------------
#define KS_ELEMS (64 * 68)
#define VS_ELEMS (64 * 72)
#define ATTN_SMEM ((2 * KS_ELEMS + 2 * VS_ELEMS) * 4)

__global__ __launch_bounds__(256) void attn_kernel()
{
    extern __shared__ float sm[];
    float* KsB = sm;
    float* VsB = sm + 2 * KS_ELEMS;

    const int qt = (SEQ / 128 - 1) - blockIdx.x;
    const int bh = blockIdx.y;
    const int q0 = qt * 128;
    const int b  = bh / NH, h = bh % NH;

    const float* qp = g_q + (size_t)bh * SEQ * DH;
    const float* kp = g_k + (size_t)bh * SEQ * DH;
    const float* vp = g_v + (size_t)bh * SEQ * DH;

    const int tid  = threadIdx.x;
    const int lane = tid & 31;
    const int w    = tid >> 5;
    const int g    = lane >> 2;
    const int t    = lane & 3;

    uint32_t qa[8][4];
    {
        const float* qr0 = qp + (size_t)(q0 + w * 16 + g) * DH;
        const float* qr1 = qr0 + 8 * DH;
#pragma unroll
        for (int kt = 0; kt < 8; kt++) {
            qa[kt][0] = f2tf(qr0[kt * 8 + t] * 0.125f);
            qa[kt][1] = f2tf(qr1[kt * 8 + t] * 0.125f);
            qa[kt][2] = f2tf(qr0[kt * 8 + t + 4] * 0.125f);
            qa[kt][3] = f2tf(qr1[kt * 8 + t + 4] * 0.125f);
        }
    }

    float o[8][4];
#pragma unroll
    for (int nt = 0; nt < 8; nt++) { o[nt][0]=o[nt][1]=o[nt][2]=o[nt][3]=0.f; }
    float m0r = -1e30f, m1r = -1e30f, l0 = 0.f, l1 = 0.f;
    const int row0 = q0 + w * 16 + g, row1 = row0 + 8;

    const int ldr = tid >> 4, ldc = tid & 15;

    float4 kreg[4], vreg[4];
#pragma unroll
    for (int i = 0; i < 4; i++) {
        int row = ldr + i * 16;
        kreg[i] = *(const float4*)&kp[(size_t)row * DH + ldc * 4];
        vreg[i] = *(const float4*)&vp[(size_t)row * DH + ldc * 4];
    }
#pragma unroll
    for (int i = 0; i < 4; i++) {
        int row = ldr + i * 16;
        float* kd = KsB + row * 68 + ldc * 4;
        float* vd = VsB + row * 72 + ldc * 4;
        kd[0]=f2tff(kreg[i].x); kd[1]=f2tff(kreg[i].y); kd[2]=f2tff(kreg[i].z); kd[3]=f2tff(kreg[i].w);
        vd[0]=f2tff(vreg[i].x); vd[1]=f2tff(vreg[i].y); vd[2]=f2tff(vreg[i].z); vd[3]=f2tff(vreg[i].w);
    }
    __syncthreads();

    const int nkt = q0 / 64 + 2;
    for (int kt2 = 0; kt2 < nkt; kt2++) {
        const int k0 = kt2 * 64;
        const int cb = kt2 & 1;
        const float* Ks = KsB + cb * KS_ELEMS;
        const float* Vs = VsB + cb * VS_ELEMS;
        const bool more = (kt2 + 1 < nkt);

        if (more) {
            const int kn = k0 + 64;
#pragma unroll
            for (int i = 0; i < 4; i++) {
                int row = kn + ldr + i * 16;
                kreg[i] = *(const float4*)&kp[(size_t)row * DH + ldc * 4];
                vreg[i] = *(const float4*)&vp[(size_t)row * DH + ldc * 4];
            }
        }

        float s[8][4];
#pragma unroll
        for (int nt = 0; nt < 8; nt++) { s[nt][0]=s[nt][1]=s[nt][2]=s[nt][3]=0.f; }
#pragma unroll
        for (int kt = 0; kt < 8; kt++)
#pragma unroll
            for (int nt = 0; nt < 8; nt++) {
                uint32_t b0 = __float_as_uint(Ks[(nt * 8 + g) * 68 + kt * 8 + t]);
                uint32_t b1 = __float_as_uint(Ks[(nt * 8 + g) * 68 + kt * 8 + t + 4]);
                mma_tf32(s[nt], qa[kt][0], qa[kt][1], qa[kt][2], qa[kt][3], b0, b1);
            }

        if (k0 + 63 > q0) {
#pragma unroll
            for (int nt = 0; nt < 8; nt++) {
                int col = k0 + nt * 8 + 2 * t;
                if (col > row0)     s[nt][0] = -1e30f;
                if (col + 1 > row0) s[nt][1] = -1e30f;
                if (col > row1)     s[nt][2] = -1e30f;
                if (col + 1 > row1) s[nt][3] = -1e30f;
            }
        }

        float mx0 = -1e30f, mx1 = -1e30f;
#pragma unroll
        for (int nt = 0; nt < 8; nt++) {
            mx0 = fmaxf(mx0, fmaxf(s[nt][0], s[nt][1]));
            mx1 = fmaxf(mx1, fmaxf(s[nt][2], s[nt][3]));
        }
        mx0 = fmaxf(mx0, __shfl_xor_sync(~0u, mx0, 1));
        mx0 = fmaxf(mx0, __shfl_xor_sync(~0u, mx0, 2));
        mx1 = fmaxf(mx1, __shfl_xor_sync(~0u, mx1, 1));
        mx1 = fmaxf(mx1, __shfl_xor_sync(~0u, mx1, 2));

        const float m0n = fmaxf(m0r, mx0), m1n = fmaxf(m1r, mx1);
        const float sc0 = __expf(m0r - m0n), sc1 = __expf(m1r - m1n);
        m0r = m0n; m1r = m1n;

        float r0 = 0.f, r1 = 0.f;
#pragma unroll
        for (int nt = 0; nt < 8; nt++) {
            s[nt][0] = __expf(s[nt][0] - m0n); s[nt][1] = __expf(s[nt][1] - m0n);
            s[nt][2] = __expf(s[nt][2] - m1n); s[nt][3] = __expf(s[nt][3] - m1n);
            r0 += s[nt][0] + s[nt][1]; r1 += s[nt][2] + s[nt][3];
        }
        r0 += __shfl_xor_sync(~0u, r0, 1); r0 += __shfl_xor_sync(~0u, r0, 2);
        r1 += __shfl_xor_sync(~0u, r1, 1); r1 += __shfl_xor_sync(~0u, r1, 2);
        l0 = l0 * sc0 + r0; l1 = l1 * sc1 + r1;

#pragma unroll
        for (int nt = 0; nt < 8; nt++) {
            o[nt][0] *= sc0; o[nt][1] *= sc0; o[nt][2] *= sc1; o[nt][3] *= sc1;
        }

        const int s0l = (lane & ~3) | (t >> 1), s1l = s0l + 2;
        const bool e = (t & 1);
#pragma unroll
        for (int kt = 0; kt < 8; kt++) {
            float v00 = __shfl_sync(~0u, s[kt][0], s0l), v01 = __shfl_sync(~0u, s[kt][1], s0l);
            float v10 = __shfl_sync(~0u, s[kt][2], s0l), v11 = __shfl_sync(~0u, s[kt][3], s0l);
            float w00 = __shfl_sync(~0u, s[kt][0], s1l), w01 = __shfl_sync(~0u, s[kt][1], s1l);
            float w10 = __shfl_sync(~0u, s[kt][2], s1l), w11 = __shfl_sync(~0u, s[kt][3], s1l);
            uint32_t pa0 = f2tf(e ? v01 : v00), pa1 = f2tf(e ? v11 : v10);
            uint32_t pa2 = f2tf(e ? w01 : w00), pa3 = f2tf(e ? w11 : w10);
#pragma unroll
            for (int nt = 0; nt < 8; nt++) {
                uint32_t b0 = __float_as_uint(Vs[(kt * 8 + t) * 72 + nt * 8 + g]);
                uint32_t b1 = __float_as_uint(Vs[(kt * 8 + t + 4) * 72 + nt * 8 + g]);
                mma_tf32(o[nt], pa0, pa1, pa2, pa3, b0, b1);
            }
        }

        if (more) {
            float* kd0 = KsB + (cb ^ 1) * KS_ELEMS;
            float* vd0 = VsB + (cb ^ 1) * VS_ELEMS;
#pragma unroll
            for (int i = 0; i < 4; i++) {
                int row = ldr + i * 16;
                float* kd = kd0 + row * 68 + ldc * 4;
                float* vd = vd0 + row * 72 + ldc * 4;
                kd[0]=f2tff(kreg[i].x); kd[1]=f2tff(kreg[i].y); kd[2]=f2tff(kreg[i].z); kd[3]=f2tff(kreg[i].w);
                vd[0]=f2tff(vreg[i].x); vd[1]=f2tff(vreg[i].y); vd[2]=f2tff(vreg[i].z); vd[3]=f2tff(vreg[i].w);
            }
            __syncthreads();
        }
    }

    const float inv0 = 1.f / l0, inv1 = 1.f / l1;
    float* or0 = g_o + ((size_t)(b * SEQ) + row0) * DM + h * DH;
    float* or1 = or0 + (size_t)8 * DM;
#pragma unroll
    for (int nt = 0; nt < 8; nt++) {
        int col = nt * 8 + 2 * t;
        float2 v0 = { o[nt][0] * inv0, o[nt][1] * inv0 };
        float2 v1 = { o[nt][2] * inv1, o[nt][3] * inv1 };
        *(float2*)&or0[col] = v0;
        *(float2*)&or1[col] = v1;
    }
}

extern "C" void kernel_launch(void* const* d_in, const int* in_sizes, int n_in,
                              void* d_out, int out_size)
{
    const float* x  = (const float*)d_in[0];
    const float* Qw = (const float*)d_in[1];
    const float* Qb = (const float*)d_in[2];
    const float* Kw = (const float*)d_in[3];
    const float* Kb = (const float*)d_in[4];
    const float* Vw = (const float*)d_in[5];
    const float* Vb = (const float*)d_in[6];
    const float* Ow = (const float*)d_in[7];
    const float* Ob = (const float*)d_in[8];
    float* out = (float*)d_out;

    static int s_init = 0;
    if (!s_init) {
        cudaFuncSetAttribute(attn_kernel,
            cudaFuncAttributeMaxDynamicSharedMemorySize, ATTN_SMEM);
        cudaFuncSetAttribute(qkv_kernel,
            cudaFuncAttributeMaxDynamicSharedMemorySize, GEMM_SMEM);
        cudaFuncSetAttribute(oproj_kernel,
            cudaFuncAttributeMaxDynamicSharedMemorySize, GEMM_SMEM);
        s_init = 1;
    }

    prep_kernel<<<dim3(32, 32, 49), 256>>>(Qw, Kw, Vw, Ow);
    qkv_kernel<<<dim3(MROWS / 128, NH / 2, 3), 256, GEMM_SMEM>>>(x, Qb, Kb, Vb);
    attn_kernel<<<dim3(SEQ / 128, BATCH * NH), 256, ATTN_SMEM>>>();
    oproj_kernel<<<dim3(MROWS / 128, DM / 128), 256, GEMM_SMEM>>>(Ob, out);
}

// round 10
// speedup vs baseline: 1.1893x; 1.1893x over previous
#include <cuda_runtime.h>
#include <cstdint>

#define BATCH 4
#define SEQ   2048
#define NH    16
#define DH    64
#define DM    1024
#define MROWS (BATCH*SEQ)

__device__ float g_q[(size_t)BATCH*NH*SEQ*DH];
__device__ float g_k[(size_t)BATCH*NH*SEQ*DH];
__device__ float g_v[(size_t)BATCH*NH*SEQ*DH];
__device__ float g_o[(size_t)MROWS*DM];

__device__ __forceinline__ uint32_t f2tf(float x) {
    uint32_t u;
    asm("cvt.rna.tf32.f32 %0, %1;" : "=r"(u) : "f"(x));
    return u;
}
__device__ __forceinline__ float f2tff(float x) { return __uint_as_float(f2tf(x)); }

__device__ __forceinline__ void mma_tf32(float* c,
    uint32_t a0, uint32_t a1, uint32_t a2, uint32_t a3,
    uint32_t b0, uint32_t b1)
{
    asm volatile(
        "mma.sync.aligned.m16n8k8.row.col.f32.tf32.tf32.f32 "
        "{%0,%1,%2,%3}, {%4,%5,%6,%7}, {%8,%9}, {%0,%1,%2,%3};"
        : "+f"(c[0]), "+f"(c[1]), "+f"(c[2]), "+f"(c[3])
        : "r"(a0), "r"(a1), "r"(a2), "r"(a3), "r"(b0), "r"(b1));
}

__device__ __forceinline__ void cp16(uint32_t sdst, const float* gsrc) {
    asm volatile("cp.async.cg.shared.global [%0], [%1], 16;"
                 :: "r"(sdst), "l"(gsrc) : "memory");
}
#define CP_COMMIT() asm volatile("cp.async.commit_group;" ::: "memory")
#define CP_WAIT(n)  asm volatile("cp.async.wait_group %0;" :: "n"(n) : "memory")

// ---------------- GEMM: block 256x128, warp 64x64, cp.async 2-stage ----------
#define GA 36
#define GB 136
#define A_FLOATS (256 * GA)                 // 9216
#define STAGE_FLOATS (A_FLOATS + 32 * GB)   // 13568
#define A_BYTES (A_FLOATS * 4)
#define STAGE_BYTES (STAGE_FLOATS * 4)      // 54272
#define GEMM_SMEM (2 * STAGE_BYTES)         // 108544

// A: row-major [m][k], stride DM, base points at (m0, 0).
// Bb: per-thread global pointer for this thread's B column word; row k at
//     Bb + k*bstride.
__device__ __forceinline__ void gemm256(
    float* sm, const float* __restrict__ Ab, const float* __restrict__ Bb,
    int bstride, float c[4][8][4])
{
    const int tid  = threadIdx.x;
    const int lane = tid & 31;
    const int w    = tid >> 5;
    const int wm   = w >> 1;        // 0..3 -> 64 rows each
    const int wn   = w & 1;         // 0..1 -> 64 cols each
    const int g    = lane >> 2;
    const int t    = lane & 3;

    const int arow = tid >> 3, ac4 = tid & 7;     // A rows arow + i*32
    const int brow = tid >> 5, bc4 = tid & 31;    // B rows brow + i*8

    uint32_t smb;
    asm("{ .reg .u64 u; cvta.to.shared.u64 u, %1; cvt.u32.u64 %0, u; }"
        : "=r"(smb) : "l"(sm));

    const uint32_t sa = smb + arow * (GA * 4) + ac4 * 16;
    const uint32_t sb = smb + A_BYTES + brow * (GB * 4) + bc4 * 16;

    // prologue: stage 0, k=0
#pragma unroll
    for (int i = 0; i < 8; i++)
        cp16(sa + i * 32 * (GA * 4), Ab + (size_t)(arow + i * 32) * DM + ac4 * 4);
#pragma unroll
    for (int i = 0; i < 4; i++)
        cp16(sb + i * 8 * (GB * 4), Bb + (size_t)(brow + i * 8) * bstride);
    CP_COMMIT();

    for (int it = 0; it < 32; it++) {
        if (it < 31) {
            const int kn = (it + 1) * 32;
            const uint32_t st = (uint32_t)(((it + 1) & 1) * STAGE_BYTES);
#pragma unroll
            for (int i = 0; i < 8; i++)
                cp16(sa + st + i * 32 * (GA * 4),
                     Ab + (size_t)(arow + i * 32) * DM + kn + ac4 * 4);
#pragma unroll
            for (int i = 0; i < 4; i++)
                cp16(sb + st + i * 8 * (GB * 4),
                     Bb + (size_t)(kn + brow + i * 8) * bstride);
            CP_COMMIT();
            CP_WAIT(1);
        } else {
            CP_WAIT(0);
        }
        __syncthreads();

        const float* As = sm + (it & 1) * STAGE_FLOATS;
        const float* Bs = As + A_FLOATS;
#pragma unroll
        for (int ks = 0; ks < 4; ks++) {
            uint32_t a[4][4];
#pragma unroll
            for (int mt = 0; mt < 4; mt++) {
                const float* ar = As + (wm * 64 + mt * 16 + g) * GA + ks * 8;
                a[mt][0] = f2tf(ar[t]);
                a[mt][1] = f2tf(ar[8 * GA + t]);
                a[mt][2] = f2tf(ar[t + 4]);
                a[mt][3] = f2tf(ar[8 * GA + t + 4]);
            }
#pragma unroll
            for (int nt = 0; nt < 8; nt++) {
                const float* br = Bs + (ks * 8 + t) * GB + wn * 64 + nt * 8 + g;
                uint32_t b0 = f2tf(br[0]);
                uint32_t b1 = f2tf(br[4 * GB]);
#pragma unroll
                for (int mt = 0; mt < 4; mt++)
                    mma_tf32(c[mt][nt], a[mt][0], a[mt][1], a[mt][2], a[mt][3], b0, b1);
            }
        }
        __syncthreads();
    }
}

// ---------------------------------------------------------------------------
// QKV projection: block 256 m-rows x 2 heads
// ---------------------------------------------------------------------------
__global__ __launch_bounds__(256, 1) void qkv_kernel(
    const float* __restrict__ X,
    const float* __restrict__ Qw, const float* __restrict__ Qb,
    const float* __restrict__ Kw, const float* __restrict__ Kb,
    const float* __restrict__ Vw, const float* __restrict__ Vb)
{
    extern __shared__ float sm[];
    const int m0    = blockIdx.x * 256;
    const int hp    = blockIdx.y;
    const int which = blockIdx.z;

    const float* W    = (which == 0 ? Qw : which == 1 ? Kw : Vw);
    const float* bias = (which == 0 ? Qb : which == 1 ? Kb : Vb);
    float* Out        = (which == 0 ? g_q : which == 1 ? g_k : g_v);

    const int bc4 = threadIdx.x & 31;
    const int bhh = 2 * hp + (bc4 >> 4);
    const int bd  = (bc4 & 15) * 4;
    const float* Bb = W + (size_t)bhh * DM * DH + bd;

    float c[4][8][4];
#pragma unroll
    for (int mt = 0; mt < 4; mt++)
#pragma unroll
        for (int nt = 0; nt < 8; nt++)
#pragma unroll
            for (int i = 0; i < 4; i++) c[mt][nt][i] = 0.f;

    gemm256(sm, X + (size_t)m0 * DM, Bb, DH, c);

    const int tid  = threadIdx.x;
    const int lane = tid & 31;
    const int w    = tid >> 5;
    const int wm   = w >> 1, wn = w & 1;
    const int g    = lane >> 2, t = lane & 3;

    const int h = 2 * hp + wn;
    const float* bi = bias + h * DH;
#pragma unroll
    for (int mt = 0; mt < 4; mt++) {
        int m = m0 + wm * 64 + mt * 16 + g;
        int b_ = m >> 11, p = m & 2047;
        float* dst = Out + (((size_t)(b_ * NH + h)) * SEQ + p) * DH;
#pragma unroll
        for (int nt = 0; nt < 8; nt++) {
            int d = nt * 8 + 2 * t;
            float bx = bi[d], by = bi[d + 1];
            float2 v0 = { c[mt][nt][0] + bx, c[mt][nt][1] + by };
            float2 v1 = { c[mt][nt][2] + bx, c[mt][nt][3] + by };
            *(float2*)&dst[d]          = v0;
            *(float2*)&dst[8 * DH + d] = v1;
        }
    }
}

// ---------------------------------------------------------------------------
// Output projection: block 256 x 128
// ---------------------------------------------------------------------------
__global__ __launch_bounds__(256, 1) void oproj_kernel(
    const float* __restrict__ Ow, const float* __restrict__ Ob,
    float* __restrict__ out)
{
    extern __shared__ float sm[];
    const int m0 = blockIdx.x * 256;
    const int n0 = blockIdx.y * 128;

    const int bc4 = threadIdx.x & 31;
    const float* Bb = Ow + n0 + bc4 * 4;

    float c[4][8][4];
#pragma unroll
    for (int mt = 0; mt < 4; mt++)
#pragma unroll
        for (int nt = 0; nt < 8; nt++)
#pragma unroll
            for (int i = 0; i < 4; i++) c[mt][nt][i] = 0.f;

    gemm256(sm, g_o + (size_t)m0 * DM, Bb, DM, c);

    const int tid  = threadIdx.x;
    const int lane = tid & 31;
    const int w    = tid >> 5;
    const int wm   = w >> 1, wn = w & 1;
    const int g    = lane >> 2, t = lane & 3;

#pragma unroll
    for (int mt = 0; mt < 4; mt++) {
        int m = m0 + wm * 64 + mt * 16 + g;
        float* dst = out + (size_t)m * DM + n0 + wn * 64;
        const float* bi = Ob + n0 + wn * 64;
#pragma unroll
        for (int nt = 0; nt < 8; nt++) {
            int d = nt * 8 + 2 * t;
            float bx = bi[d], by = bi[d + 1];
            float2 v0 = { c[mt][nt][0] + bx, c[mt][nt][1] + by };
            float2 v1 = { c[mt][nt][2] + bx, c[mt][nt][3] + by };
            *(float2*)&dst[d]          = v0;
            *(float2*)&dst[8 * DM + d] = v1;
        }
    }
}

// ---------------------------------------------------------------------------
// Causal flash attention (R8 verbatim: double-buffered, 1 sync/tile)
// ---------------------------------------------------------------------------
#define KS_ELEMS (64 * 68)
#define VS_ELEMS (64 * 72)
#define ATTN_SMEM ((2 * KS_ELEMS + 2 * VS_ELEMS) * 4)

__global__ __launch_bounds__(256) void attn_kernel()
{
    extern __shared__ float sm[];
    float* KsB = sm;
    float* VsB = sm + 2 * KS_ELEMS;

    const int qt = (SEQ / 128 - 1) - blockIdx.x;
    const int bh = blockIdx.y;
    const int q0 = qt * 128;
    const int b  = bh / NH, h = bh % NH;

    const float* qp = g_q + (size_t)bh * SEQ * DH;
    const float* kp = g_k + (size_t)bh * SEQ * DH;
    const float* vp = g_v + (size_t)bh * SEQ * DH;

    const int tid  = threadIdx.x;
    const int lane = tid & 31;
    const int w    = tid >> 5;
    const int g    = lane >> 2;
    const int t    = lane & 3;

    uint32_t qa[8][4];
    {
        const float* qr0 = qp + (size_t)(q0 + w * 16 + g) * DH;
        const float* qr1 = qr0 + 8 * DH;
#pragma unroll
        for (int kt = 0; kt < 8; kt++) {
            qa[kt][0] = f2tf(qr0[kt * 8 + t] * 0.125f);
            qa[kt][1] = f2tf(qr1[kt * 8 + t] * 0.125f);
            qa[kt][2] = f2tf(qr0[kt * 8 + t + 4] * 0.125f);
            qa[kt][3] = f2tf(qr1[kt * 8 + t + 4] * 0.125f);
        }
    }

    float o[8][4];
#pragma unroll
    for (int nt = 0; nt < 8; nt++) { o[nt][0]=o[nt][1]=o[nt][2]=o[nt][3]=0.f; }
    float m0r = -1e30f, m1r = -1e30f, l0 = 0.f, l1 = 0.f;
    const int row0 = q0 + w * 16 + g, row1 = row0 + 8;

    const int ldr = tid >> 4, ldc = tid & 15;

    float4 kreg[4], vreg[4];
#pragma unroll
    for (int i = 0; i < 4; i++) {
        int row = ldr + i * 16;
        kreg[i] = *(const float4*)&kp[(size_t)row * DH + ldc * 4];
        vreg[i] = *(const float4*)&vp[(size_t)row * DH + ldc * 4];
    }
#pragma unroll
    for (int i = 0; i < 4; i++) {
        int row = ldr + i * 16;
        float* kd = KsB + row * 68 + ldc * 4;
        float* vd = VsB + row * 72 + ldc * 4;
        kd[0]=f2tff(kreg[i].x); kd[1]=f2tff(kreg[i].y); kd[2]=f2tff(kreg[i].z); kd[3]=f2tff(kreg[i].w);
        vd[0]=f2tff(vreg[i].x); vd[1]=f2tff(vreg[i].y); vd[2]=f2tff(vreg[i].z); vd[3]=f2tff(vreg[i].w);
    }
    __syncthreads();

    const int nkt = q0 / 64 + 2;
    for (int kt2 = 0; kt2 < nkt; kt2++) {
        const int k0 = kt2 * 64;
        const int cb = kt2 & 1;
        const float* Ks = KsB + cb * KS_ELEMS;
        const float* Vs = VsB + cb * VS_ELEMS;
        const bool more = (kt2 + 1 < nkt);

        if (more) {
            const int kn = k0 + 64;
#pragma unroll
            for (int i = 0; i < 4; i++) {
                int row = kn + ldr + i * 16;
                kreg[i] = *(const float4*)&kp[(size_t)row * DH + ldc * 4];
                vreg[i] = *(const float4*)&vp[(size_t)row * DH + ldc * 4];
            }
        }

        float s[8][4];
#pragma unroll
        for (int nt = 0; nt < 8; nt++) { s[nt][0]=s[nt][1]=s[nt][2]=s[nt][3]=0.f; }
#pragma unroll
        for (int kt = 0; kt < 8; kt++)
#pragma unroll
            for (int nt = 0; nt < 8; nt++) {
                uint32_t b0 = __float_as_uint(Ks[(nt * 8 + g) * 68 + kt * 8 + t]);
                uint32_t b1 = __float_as_uint(Ks[(nt * 8 + g) * 68 + kt * 8 + t + 4]);
                mma_tf32(s[nt], qa[kt][0], qa[kt][1], qa[kt][2], qa[kt][3], b0, b1);
            }

        if (k0 + 63 > q0) {
#pragma unroll
            for (int nt = 0; nt < 8; nt++) {
                int col = k0 + nt * 8 + 2 * t;
                if (col > row0)     s[nt][0] = -1e30f;
                if (col + 1 > row0) s[nt][1] = -1e30f;
                if (col > row1)     s[nt][2] = -1e30f;
                if (col + 1 > row1) s[nt][3] = -1e30f;
            }
        }

        float mx0 = -1e30f, mx1 = -1e30f;
#pragma unroll
        for (int nt = 0; nt < 8; nt++) {
            mx0 = fmaxf(mx0, fmaxf(s[nt][0], s[nt][1]));
            mx1 = fmaxf(mx1, fmaxf(s[nt][2], s[nt][3]));
        }
        mx0 = fmaxf(mx0, __shfl_xor_sync(~0u, mx0, 1));
        mx0 = fmaxf(mx0, __shfl_xor_sync(~0u, mx0, 2));
        mx1 = fmaxf(mx1, __shfl_xor_sync(~0u, mx1, 1));
        mx1 = fmaxf(mx1, __shfl_xor_sync(~0u, mx1, 2));

        const float m0n = fmaxf(m0r, mx0), m1n = fmaxf(m1r, mx1);
        const float sc0 = __expf(m0r - m0n), sc1 = __expf(m1r - m1n);
        m0r = m0n; m1r = m1n;

        float r0 = 0.f, r1 = 0.f;
#pragma unroll
        for (int nt = 0; nt < 8; nt++) {
            s[nt][0] = __expf(s[nt][0] - m0n); s[nt][1] = __expf(s[nt][1] - m0n);
            s[nt][2] = __expf(s[nt][2] - m1n); s[nt][3] = __expf(s[nt][3] - m1n);
            r0 += s[nt][0] + s[nt][1]; r1 += s[nt][2] + s[nt][3];
        }
        r0 += __shfl_xor_sync(~0u, r0, 1); r0 += __shfl_xor_sync(~0u, r0, 2);
        r1 += __shfl_xor_sync(~0u, r1, 1); r1 += __shfl_xor_sync(~0u, r1, 2);
        l0 = l0 * sc0 + r0; l1 = l1 * sc1 + r1;

#pragma unroll
        for (int nt = 0; nt < 8; nt++) {
            o[nt][0] *= sc0; o[nt][1] *= sc0; o[nt][2] *= sc1; o[nt][3] *= sc1;
        }

        const int s0l = (lane & ~3) | (t >> 1), s1l = s0l + 2;
        const bool e = (t & 1);
#pragma unroll
        for (int kt = 0; kt < 8; kt++) {
            float v00 = __shfl_sync(~0u, s[kt][0], s0l), v01 = __shfl_sync(~0u, s[kt][1], s0l);
            float v10 = __shfl_sync(~0u, s[kt][2], s0l), v11 = __shfl_sync(~0u, s[kt][3], s0l);
            float w00 = __shfl_sync(~0u, s[kt][0], s1l), w01 = __shfl_sync(~0u, s[kt][1], s1l);
            float w10 = __shfl_sync(~0u, s[kt][2], s1l), w11 = __shfl_sync(~0u, s[kt][3], s1l);
            uint32_t pa0 = f2tf(e ? v01 : v00), pa1 = f2tf(e ? v11 : v10);
            uint32_t pa2 = f2tf(e ? w01 : w00), pa3 = f2tf(e ? w11 : w10);
#pragma unroll
            for (int nt = 0; nt < 8; nt++) {
                uint32_t b0 = __float_as_uint(Vs[(kt * 8 + t) * 72 + nt * 8 + g]);
                uint32_t b1 = __float_as_uint(Vs[(kt * 8 + t + 4) * 72 + nt * 8 + g]);
                mma_tf32(o[nt], pa0, pa1, pa2, pa3, b0, b1);
            }
        }

        if (more) {
            float* kd0 = KsB + (cb ^ 1) * KS_ELEMS;
            float* vd0 = VsB + (cb ^ 1) * VS_ELEMS;
#pragma unroll
            for (int i = 0; i < 4; i++) {
                int row = ldr + i * 16;
                float* kd = kd0 + row * 68 + ldc * 4;
                float* vd = vd0 + row * 72 + ldc * 4;
                kd[0]=f2tff(kreg[i].x); kd[1]=f2tff(kreg[i].y); kd[2]=f2tff(kreg[i].z); kd[3]=f2tff(kreg[i].w);
                vd[0]=f2tff(vreg[i].x); vd[1]=f2tff(vreg[i].y); vd[2]=f2tff(vreg[i].z); vd[3]=f2tff(vreg[i].w);
            }
            __syncthreads();
        }
    }

    const float inv0 = 1.f / l0, inv1 = 1.f / l1;
    float* or0 = g_o + ((size_t)(b * SEQ) + row0) * DM + h * DH;
    float* or1 = or0 + (size_t)8 * DM;
#pragma unroll
    for (int nt = 0; nt < 8; nt++) {
        int col = nt * 8 + 2 * t;
        float2 v0 = { o[nt][0] * inv0, o[nt][1] * inv0 };
        float2 v1 = { o[nt][2] * inv1, o[nt][3] * inv1 };
        *(float2*)&or0[col] = v0;
        *(float2*)&or1[col] = v1;
    }
}

extern "C" void kernel_launch(void* const* d_in, const int* in_sizes, int n_in,
                              void* d_out, int out_size)
{
    const float* x  = (const float*)d_in[0];
    const float* Qw = (const float*)d_in[1];
    const float* Qb = (const float*)d_in[2];
    const float* Kw = (const float*)d_in[3];
    const float* Kb = (const float*)d_in[4];
    const float* Vw = (const float*)d_in[5];
    const float* Vb = (const float*)d_in[6];
    const float* Ow = (const float*)d_in[7];
    const float* Ob = (const float*)d_in[8];
    float* out = (float*)d_out;

    static int s_init = 0;
    if (!s_init) {
        cudaFuncSetAttribute(attn_kernel,
            cudaFuncAttributeMaxDynamicSharedMemorySize, ATTN_SMEM);
        cudaFuncSetAttribute(qkv_kernel,
            cudaFuncAttributeMaxDynamicSharedMemorySize, GEMM_SMEM);
        cudaFuncSetAttribute(oproj_kernel,
            cudaFuncAttributeMaxDynamicSharedMemorySize, GEMM_SMEM);
        s_init = 1;
    }

    qkv_kernel<<<dim3(MROWS / 256, NH / 2, 3), 256, GEMM_SMEM>>>(x, Qw, Qb, Kw, Kb, Vw, Vb);
    attn_kernel<<<dim3(SEQ / 128, BATCH * NH), 256, ATTN_SMEM>>>();
    oproj_kernel<<<dim3(MROWS / 256, DM / 128), 256, GEMM_SMEM>>>(Ow, Ob, out);
}

// round 12
// speedup vs baseline: 1.3307x; 1.1189x over previous
#include <cuda_runtime.h>
#include <cstdint>

#define BATCH 4
#define SEQ   2048
#define NH    16
#define DH    64
#define DM    1024
#define MROWS (BATCH*SEQ)

__device__ float g_q[(size_t)BATCH*NH*SEQ*DH];
__device__ float g_k[(size_t)BATCH*NH*SEQ*DH];
__device__ float g_v[(size_t)BATCH*NH*SEQ*DH];
__device__ float g_o[(size_t)MROWS*DM];
__device__ float g_xr[(size_t)MROWS*DM];      // rounded X
__device__ float g_wr[(size_t)3*NH*DM*DH];    // rounded QKV weights
__device__ float g_owr[(size_t)DM*DM];        // rounded O weights

__device__ __forceinline__ uint32_t f2tf(float x) {
    uint32_t u;
    asm("cvt.rna.tf32.f32 %0, %1;" : "=r"(u) : "f"(x));
    return u;
}
__device__ __forceinline__ float f2tff(float x) { return __uint_as_float(f2tf(x)); }

__device__ __forceinline__ void mma_tf32(float* c,
    uint32_t a0, uint32_t a1, uint32_t a2, uint32_t a3,
    uint32_t b0, uint32_t b1)
{
    asm volatile(
        "mma.sync.aligned.m16n8k8.row.col.f32.tf32.tf32.f32 "
        "{%0,%1,%2,%3}, {%4,%5,%6,%7}, {%8,%9}, {%0,%1,%2,%3};"
        : "+f"(c[0]), "+f"(c[1]), "+f"(c[2]), "+f"(c[3])
        : "r"(a0), "r"(a1), "r"(a2), "r"(a3), "r"(b0), "r"(b1));
}

__device__ __forceinline__ void cp16(uint32_t sdst, const float* gsrc) {
    asm volatile("cp.async.cg.shared.global [%0], [%1], 16;"
                 :: "r"(sdst), "l"(gsrc) : "memory");
}
#define CP_COMMIT() asm volatile("cp.async.commit_group;" ::: "memory")
#define CP_WAIT(n)  asm volatile("cp.async.wait_group %0;" :: "n"(n) : "memory")

// ---------------------------------------------------------------------------
// prep: round inputs to tf32 once (idempotent; numerics identical to in-loop)
// ---------------------------------------------------------------------------
__global__ __launch_bounds__(256) void prep_kernel(
    const float* __restrict__ X,
    const float* __restrict__ Qw, const float* __restrict__ Kw,
    const float* __restrict__ Vw, const float* __restrict__ Ow)
{
    const int z = blockIdx.z;
    const float* src; float* dst; size_t n;
    if (z == 0)      { src = X;  dst = g_xr;  n = (size_t)MROWS * DM; }
    else if (z == 4) { src = Ow; dst = g_owr; n = (size_t)DM * DM; }
    else {
        src = (z == 1 ? Qw : z == 2 ? Kw : Vw);
        dst = g_wr + (size_t)(z - 1) * NH * DM * DH;
        n = (size_t)NH * DM * DH;
    }
    const size_t stride = (size_t)gridDim.x * blockDim.x * 4;
    for (size_t i = ((size_t)blockIdx.x * blockDim.x + threadIdx.x) * 4; i < n; i += stride) {
        float4 v = *(const float4*)&src[i];
        v.x = f2tff(v.x); v.y = f2tff(v.y); v.z = f2tff(v.z); v.w = f2tff(v.w);
        *(float4*)&dst[i] = v;
    }
}

// ---------------------------------------------------------------------------
// GEMM: block 128x128, warp 32x64, 3-stage cp.async, wait -> sync -> issue.
// ---------------------------------------------------------------------------
#define GA 36
#define GB 136
#define A_FLOATS (128 * GA)                 // 4608
#define STG_FLOATS (A_FLOATS + 32 * GB)     // 8960
#define STG_BYTES (STG_FLOATS * 4)          // 35840
#define GEMM_SMEM (3 * STG_BYTES)           // 107520

__device__ __forceinline__ void gemm128(
    float* sm, const float* __restrict__ Ab, const float* __restrict__ Bb,
    int bstride, float c[2][8][4])
{
    const int tid  = threadIdx.x;
    const int lane = tid & 31;
    const int w    = tid >> 5;
    const int wm   = w >> 1;
    const int wn   = w & 1;
    const int g    = lane >> 2;
    const int t    = lane & 3;

    const int arow = tid >> 3, ac4 = tid & 7;
    const int brow = tid >> 5;

    uint32_t smb;
    asm("{ .reg .u64 u; cvta.to.shared.u64 u, %1; cvt.u32.u64 %0, u; }"
        : "=r"(smb) : "l"(sm));
    const uint32_t sa = smb + arow * (GA * 4) + ac4 * 16;
    const uint32_t sb = smb + A_FLOATS * 4 + brow * (GB * 4) + (tid & 31) * 16;

    // prologue: stages 0,1
#pragma unroll
    for (int s = 0; s < 2; s++) {
        const int k0 = s * 32;
        const uint32_t so = (uint32_t)(s * STG_BYTES);
#pragma unroll
        for (int i = 0; i < 4; i++)
            cp16(sa + so + i * 32 * (GA * 4), Ab + (size_t)(arow + i * 32) * DM + k0 + ac4 * 4);
#pragma unroll
        for (int i = 0; i < 4; i++)
            cp16(sb + so + i * 8 * (GB * 4), Bb + (size_t)(k0 + brow + i * 8) * bstride);
        CP_COMMIT();
    }

    for (int it = 0; it < 32; it++) {
        // 1) own-thread completion of stage it
        if (it < 31) { CP_WAIT(1); } else { CP_WAIT(0); }
        // 2) cross-thread visibility
        __syncthreads();
        // 3) refill buffer (it-1)%3 with stage it+2 (everyone is past iter it-1)
        if (it + 2 < 32) {
            const int k0 = (it + 2) * 32;
            const uint32_t so = (uint32_t)(((it + 2) % 3) * STG_BYTES);
#pragma unroll
            for (int i = 0; i < 4; i++)
                cp16(sa + so + i * 32 * (GA * 4), Ab + (size_t)(arow + i * 32) * DM + k0 + ac4 * 4);
#pragma unroll
            for (int i = 0; i < 4; i++)
                cp16(sb + so + i * 8 * (GB * 4), Bb + (size_t)(k0 + brow + i * 8) * bstride);
            CP_COMMIT();
        }
        // 4) compute stage it
        const float* As = sm + (it % 3) * STG_FLOATS;
        const float* Bs = As + A_FLOATS;
#pragma unroll
        for (int ks = 0; ks < 4; ks++) {
            uint32_t a[2][4];
#pragma unroll
            for (int mt = 0; mt < 2; mt++) {
                const float* ar = As + (wm * 32 + mt * 16 + g) * GA + ks * 8;
                a[mt][0] = __float_as_uint(ar[t]);
                a[mt][1] = __float_as_uint(ar[8 * GA + t]);
                a[mt][2] = __float_as_uint(ar[t + 4]);
                a[mt][3] = __float_as_uint(ar[8 * GA + t + 4]);
            }
#pragma unroll
            for (int nt = 0; nt < 8; nt++) {
                const float* br = Bs + (ks * 8 + t) * GB + wn * 64 + nt * 8 + g;
                uint32_t b0 = __float_as_uint(br[0]);
                uint32_t b1 = __float_as_uint(br[4 * GB]);
#pragma unroll
                for (int mt = 0; mt < 2; mt++)
                    mma_tf32(c[mt][nt], a[mt][0], a[mt][1], a[mt][2], a[mt][3], b0, b1);
            }
        }
    }
}

// ---------------------------------------------------------------------------
// QKV: block 128 m-rows x 2 heads; epilogue writes tf32-rounded (c+bias)
// ---------------------------------------------------------------------------
__global__ __launch_bounds__(256, 2) void qkv_kernel(
    const float* __restrict__ Qb, const float* __restrict__ Kb,
    const float* __restrict__ Vb)
{
    extern __shared__ float sm[];
    const int m0    = blockIdx.x * 128;
    const int hp    = blockIdx.y;
    const int which = blockIdx.z;

    const float* bias = (which == 0 ? Qb : which == 1 ? Kb : Vb);
    float* Out        = (which == 0 ? g_q : which == 1 ? g_k : g_v);
    const float* W    = g_wr + (size_t)which * NH * DM * DH;

    const int bc4 = threadIdx.x & 31;
    const int bhh = 2 * hp + (bc4 >> 4);
    const float* Bb = W + (size_t)bhh * DM * DH + (bc4 & 15) * 4;

    float c[2][8][4];
#pragma unroll
    for (int mt = 0; mt < 2; mt++)
#pragma unroll
        for (int nt = 0; nt < 8; nt++)
#pragma unroll
            for (int i = 0; i < 4; i++) c[mt][nt][i] = 0.f;

    gemm128(sm, g_xr + (size_t)m0 * DM, Bb, DH, c);

    const int tid  = threadIdx.x;
    const int lane = tid & 31;
    const int w    = tid >> 5;
    const int wm   = w >> 1, wn = w & 1;
    const int g    = lane >> 2, t = lane & 3;

    const int h = 2 * hp + wn;
    const float* bi = bias + h * DH;
#pragma unroll
    for (int mt = 0; mt < 2; mt++) {
        int m = m0 + wm * 32 + mt * 16 + g;
        int b_ = m >> 11, p = m & 2047;
        float* dst = Out + (((size_t)(b_ * NH + h)) * SEQ + p) * DH;
#pragma unroll
        for (int nt = 0; nt < 8; nt++) {
            int d = nt * 8 + 2 * t;
            float bx = bi[d], by = bi[d + 1];
            float2 v0 = { f2tff(c[mt][nt][0] + bx), f2tff(c[mt][nt][1] + by) };
            float2 v1 = { f2tff(c[mt][nt][2] + bx), f2tff(c[mt][nt][3] + by) };
            *(float2*)&dst[d]          = v0;
            *(float2*)&dst[8 * DH + d] = v1;
        }
    }
}

// ---------------------------------------------------------------------------
// O-proj: block 128x128; final output fp32 (no rounding)
// ---------------------------------------------------------------------------
__global__ __launch_bounds__(256, 2) void oproj_kernel(
    const float* __restrict__ Ob, float* __restrict__ out)
{
    extern __shared__ float sm[];
    const int m0 = blockIdx.x * 128;
    const int n0 = blockIdx.y * 128;

    const float* Bb = g_owr + n0 + (threadIdx.x & 31) * 4;

    float c[2][8][4];
#pragma unroll
    for (int mt = 0; mt < 2; mt++)
#pragma unroll
        for (int nt = 0; nt < 8; nt++)
#pragma unroll
            for (int i = 0; i < 4; i++) c[mt][nt][i] = 0.f;

    gemm128(sm, g_o + (size_t)m0 * DM, Bb, DM, c);

    const int tid  = threadIdx.x;
    const int lane = tid & 31;
    const int w    = tid >> 5;
    const int wm   = w >> 1, wn = w & 1;
    const int g    = lane >> 2, t = lane & 3;

#pragma unroll
    for (int mt = 0; mt < 2; mt++) {
        int m = m0 + wm * 32 + mt * 16 + g;
        float* dst = out + (size_t)m * DM + n0 + wn * 64;
        const float* bi = Ob + n0 + wn * 64;
#pragma unroll
        for (int nt = 0; nt < 8; nt++) {
            int d = nt * 8 + 2 * t;
            float bx = bi[d], by = bi[d + 1];
            float2 v0 = { c[mt][nt][0] + bx, c[mt][nt][1] + by };
            float2 v1 = { c[mt][nt][2] + bx, c[mt][nt][3] + by };
            *(float2*)&dst[d]          = v0;
            *(float2*)&dst[8 * DM + d] = v1;
        }
    }
}

// ---------------------------------------------------------------------------
// Causal flash attention: tf32 mma, 3-stage cp.async K/V, wait -> sync -> issue
// ---------------------------------------------------------------------------
#define KSF 68
#define VSF 72
#define KV_FLOATS (64 * KSF + 64 * VSF)    // 8960
#define KV_BYTES (KV_FLOATS * 4)           // 35840
#define ATTN_SMEM (3 * KV_BYTES)           // 107520

__global__ __launch_bounds__(256, 2) void attn_kernel()
{
    extern __shared__ float sm[];

    const int qt = (SEQ / 128 - 1) - blockIdx.x;
    const int bh = blockIdx.y;
    const int q0 = qt * 128;
    const int b  = bh / NH, h = bh % NH;

    const float* qp = g_q + (size_t)bh * SEQ * DH;
    const float* kp = g_k + (size_t)bh * SEQ * DH;
    const float* vp = g_v + (size_t)bh * SEQ * DH;

    const int tid  = threadIdx.x;
    const int lane = tid & 31;
    const int w    = tid >> 5;
    const int g    = lane >> 2;
    const int t    = lane & 3;

    uint32_t smb;
    asm("{ .reg .u64 u; cvta.to.shared.u64 u, %1; cvt.u32.u64 %0, u; }"
        : "=r"(smb) : "l"(sm));

    const int ldr = tid >> 4, ldc = tid & 15;
    const uint32_t kdst = smb + ldr * (KSF * 4) + ldc * 16;
    const uint32_t vdst = smb + 64 * KSF * 4 + ldr * (VSF * 4) + ldc * 16;

    const int nkt = q0 / 64 + 2;

    // prologue: stages 0,1
#pragma unroll
    for (int s = 0; s < 2; s++) {
        const int k0 = s * 64;
        const uint32_t so = (uint32_t)(s * KV_BYTES);
#pragma unroll
        for (int i = 0; i < 4; i++) {
            int row = ldr + i * 16;
            cp16(kdst + so + i * 16 * (KSF * 4), kp + (size_t)(k0 + row) * DH + ldc * 4);
            cp16(vdst + so + i * 16 * (VSF * 4), vp + (size_t)(k0 + row) * DH + ldc * 4);
        }
        CP_COMMIT();
    }

    // Q fragments (pre-rounded; *0.125 exact)
    uint32_t qa[8][4];
    {
        const float* qr0 = qp + (size_t)(q0 + w * 16 + g) * DH;
        const float* qr1 = qr0 + 8 * DH;
#pragma unroll
        for (int kt = 0; kt < 8; kt++) {
            qa[kt][0] = __float_as_uint(qr0[kt * 8 + t] * 0.125f);
            qa[kt][1] = __float_as_uint(qr1[kt * 8 + t] * 0.125f);
            qa[kt][2] = __float_as_uint(qr0[kt * 8 + t + 4] * 0.125f);
            qa[kt][3] = __float_as_uint(qr1[kt * 8 + t + 4] * 0.125f);
        }
    }

    float o[8][4];
#pragma unroll
    for (int nt = 0; nt < 8; nt++) { o[nt][0]=o[nt][1]=o[nt][2]=o[nt][3]=0.f; }
    float m0r = -1e30f, m1r = -1e30f, l0 = 0.f, l1 = 0.f;
    const int row0 = q0 + w * 16 + g, row1 = row0 + 8;

    for (int kt2 = 0; kt2 < nkt; kt2++) {
        const int k0 = kt2 * 64;
        if (kt2 + 1 < nkt) { CP_WAIT(1); } else { CP_WAIT(0); }
        __syncthreads();
        if (kt2 + 2 < nkt) {
            const int kn = (kt2 + 2) * 64;
            const uint32_t so = (uint32_t)(((kt2 + 2) % 3) * KV_BYTES);
#pragma unroll
            for (int i = 0; i < 4; i++) {
                int row = ldr + i * 16;
                cp16(kdst + so + i * 16 * (KSF * 4), kp + (size_t)(kn + row) * DH + ldc * 4);
                cp16(vdst + so + i * 16 * (VSF * 4), vp + (size_t)(kn + row) * DH + ldc * 4);
            }
            CP_COMMIT();
        }

        const float* Ks = sm + (kt2 % 3) * KV_FLOATS;
        const float* Vs = Ks + 64 * KSF;

        float s[8][4];
#pragma unroll
        for (int nt = 0; nt < 8; nt++) { s[nt][0]=s[nt][1]=s[nt][2]=s[nt][3]=0.f; }
#pragma unroll
        for (int kt = 0; kt < 8; kt++)
#pragma unroll
            for (int nt = 0; nt < 8; nt++) {
                uint32_t b0 = __float_as_uint(Ks[(nt * 8 + g) * KSF + kt * 8 + t]);
                uint32_t b1 = __float_as_uint(Ks[(nt * 8 + g) * KSF + kt * 8 + t + 4]);
                mma_tf32(s[nt], qa[kt][0], qa[kt][1], qa[kt][2], qa[kt][3], b0, b1);
            }

        if (k0 + 63 > q0) {
#pragma unroll
            for (int nt = 0; nt < 8; nt++) {
                int col = k0 + nt * 8 + 2 * t;
                if (col > row0)     s[nt][0] = -1e30f;
                if (col + 1 > row0) s[nt][1] = -1e30f;
                if (col > row1)     s[nt][2] = -1e30f;
                if (col + 1 > row1) s[nt][3] = -1e30f;
            }
        }

        float mx0 = -1e30f, mx1 = -1e30f;
#pragma unroll
        for (int nt = 0; nt < 8; nt++) {
            mx0 = fmaxf(mx0, fmaxf(s[nt][0], s[nt][1]));
            mx1 = fmaxf(mx1, fmaxf(s[nt][2], s[nt][3]));
        }
        mx0 = fmaxf(mx0, __shfl_xor_sync(~0u, mx0, 1));
        mx0 = fmaxf(mx0, __shfl_xor_sync(~0u, mx0, 2));
        mx1 = fmaxf(mx1, __shfl_xor_sync(~0u, mx1, 1));
        mx1 = fmaxf(mx1, __shfl_xor_sync(~0u, mx1, 2));

        const float m0n = fmaxf(m0r, mx0), m1n = fmaxf(m1r, mx1);
        const float sc0 = __expf(m0r - m0n), sc1 = __expf(m1r - m1n);
        m0r = m0n; m1r = m1n;

        float r0 = 0.f, r1 = 0.f;
#pragma unroll
        for (int nt = 0; nt < 8; nt++) {
            s[nt][0] = __expf(s[nt][0] - m0n); s[nt][1] = __expf(s[nt][1] - m0n);
            s[nt][2] = __expf(s[nt][2] - m1n); s[nt][3] = __expf(s[nt][3] - m1n);
            r0 += s[nt][0] + s[nt][1]; r1 += s[nt][2] + s[nt][3];
        }
        r0 += __shfl_xor_sync(~0u, r0, 1); r0 += __shfl_xor_sync(~0u, r0, 2);
        r1 += __shfl_xor_sync(~0u, r1, 1); r1 += __shfl_xor_sync(~0u, r1, 2);
        l0 = l0 * sc0 + r0; l1 = l1 * sc1 + r1;

#pragma unroll
        for (int nt = 0; nt < 8; nt++) {
            o[nt][0] *= sc0; o[nt][1] *= sc0; o[nt][2] *= sc1; o[nt][3] *= sc1;
        }

        const int s0l = (lane & ~3) | (t >> 1), s1l = s0l + 2;
        const bool e = (t & 1);
#pragma unroll
        for (int kt = 0; kt < 8; kt++) {
            float v00 = __shfl_sync(~0u, s[kt][0], s0l), v01 = __shfl_sync(~0u, s[kt][1], s0l);
            float v10 = __shfl_sync(~0u, s[kt][2], s0l), v11 = __shfl_sync(~0u, s[kt][3], s0l);
            float w00 = __shfl_sync(~0u, s[kt][0], s1l), w01 = __shfl_sync(~0u, s[kt][1], s1l);
            float w10 = __shfl_sync(~0u, s[kt][2], s1l), w11 = __shfl_sync(~0u, s[kt][3], s1l);
            uint32_t pa0 = f2tf(e ? v01 : v00), pa1 = f2tf(e ? v11 : v10);
            uint32_t pa2 = f2tf(e ? w01 : w00), pa3 = f2tf(e ? w11 : w10);
#pragma unroll
            for (int nt = 0; nt < 8; nt++) {
                uint32_t b0 = __float_as_uint(Vs[(kt * 8 + t) * VSF + nt * 8 + g]);
                uint32_t b1 = __float_as_uint(Vs[(kt * 8 + t + 4) * VSF + nt * 8 + g]);
                mma_tf32(o[nt], pa0, pa1, pa2, pa3, b0, b1);
            }
        }
    }

    const float inv0 = 1.f / l0, inv1 = 1.f / l1;
    float* or0 = g_o + ((size_t)(b * SEQ) + row0) * DM + h * DH;
    float* or1 = or0 + (size_t)8 * DM;
#pragma unroll
    for (int nt = 0; nt < 8; nt++) {
        int col = nt * 8 + 2 * t;
        float2 v0 = { f2tff(o[nt][0] * inv0), f2tff(o[nt][1] * inv0) };
        float2 v1 = { f2tff(o[nt][2] * inv1), f2tff(o[nt][3] * inv1) };
        *(float2*)&or0[col] = v0;
        *(float2*)&or1[col] = v1;
    }
}

extern "C" void kernel_launch(void* const* d_in, const int* in_sizes, int n_in,
                              void* d_out, int out_size)
{
    const float* x  = (const float*)d_in[0];
    const float* Qw = (const float*)d_in[1];
    const float* Qb = (const float*)d_in[2];
    const float* Kw = (const float*)d_in[3];
    const float* Kb = (const float*)d_in[4];
    const float* Vw = (const float*)d_in[5];
    const float* Vb = (const float*)d_in[6];
    const float* Ow = (const float*)d_in[7];
    const float* Ob = (const float*)d_in[8];
    float* out = (float*)d_out;

    static int s_init = 0;
    if (!s_init) {
        cudaFuncSetAttribute(attn_kernel,
            cudaFuncAttributeMaxDynamicSharedMemorySize, ATTN_SMEM);
        cudaFuncSetAttribute(qkv_kernel,
            cudaFuncAttributeMaxDynamicSharedMemorySize, GEMM_SMEM);
        cudaFuncSetAttribute(oproj_kernel,
            cudaFuncAttributeMaxDynamicSharedMemorySize, GEMM_SMEM);
        s_init = 1;
    }

    prep_kernel<<<dim3(256, 1, 5), 256>>>(x, Qw, Kw, Vw, Ow);
    qkv_kernel<<<dim3(MROWS / 128, NH / 2, 3), 256, GEMM_SMEM>>>(Qb, Kb, Vb);
    attn_kernel<<<dim3(SEQ / 128, BATCH * NH), 256, ATTN_SMEM>>>();
    oproj_kernel<<<dim3(MROWS / 128, DM / 128), 256, GEMM_SMEM>>>(Ob, out);
}